// round 14
// baseline (speedup 1.0000x reference)
#include <cuda_runtime.h>
#include <cuda_bf16.h>
#include <math.h>

// ---------------------------------------------------------------------------
// Problem constants (fixed shapes from metadata)
// ---------------------------------------------------------------------------
#define BATCH   2
#define NPTS    8192
#define CHUNKS  32
#define CHUNK_SZ (NPTS / CHUNKS)   // 256
#define TILE    256
#define QBLK    4                  // queries per thread
#define XTILES  (NPTS / (256 * QBLK))   // 8

#define VD 64
#define VH 128
#define VW 128
#define VOL_PER_B (VD * VH * VW)
#define DCHUNK 4

#define DH 512
#define DW 512
#define DPIX_PER_B (DH * DW)
#define DPIX_TOT   (BATCH * DPIX_PER_B)

// mega-kernel block partition: TYPE-SEGREGATED, chamfer (longest jobs) first.
// (Interleave experiment r9 regressed 10us; segregated measured best r4/6/8.)
#define CH_BLOCKS 1024
#define CL_BLOCKS 512
#define DP_BLOCKS 512
#define ALL_BLOCKS (CH_BLOCKS + CL_BLOCKS + DP_BLOCKS)   // 2048

#define NMIN (4 * NPTS)            // [dir][b][pt] min table, 32768 entries

// ---------------------------------------------------------------------------
// Device scratch (static — no allocations allowed)
// ---------------------------------------------------------------------------
struct Acc {
    double inter[2], psum[2], gsum[2];
    double g_sum[2], g2_sum[2];
    double gradx, grady, mask_num, mask_den;
};
#define ACC_N 14
__device__ Acc g_acc;                 // zero-init; re-zeroed by finalize kernel
__device__ unsigned int g_min[NMIN];  // zero-init (= +inf identity); reset by finalize

// ---------------------------------------------------------------------------
// Monotone float<->uint encoding: min over floats == max over codes, with 0
// as the identity (no real float encodes to 0).
// ---------------------------------------------------------------------------
__device__ __forceinline__ unsigned int enc_min(float f) {
    unsigned int u = __float_as_uint(f);
    return (u & 0x80000000u) ? u : ((~u) & 0x7FFFFFFFu);
}
__device__ __forceinline__ float dec_min(unsigned int rk) {
    return (rk & 0x80000000u) ? __uint_as_float(rk)
                              : __uint_as_float((~rk) & 0x7FFFFFFFu);
}

// ---------------------------------------------------------------------------
// f32x2 packed helpers (sm_103a; ptxas will not auto-fuse — must be PTX)
// ---------------------------------------------------------------------------
__device__ __forceinline__ unsigned long long fma2(unsigned long long a,
                                                   unsigned long long b,
                                                   unsigned long long c) {
    unsigned long long d;
    asm("fma.rn.f32x2 %0, %1, %2, %3;" : "=l"(d) : "l"(a), "l"(b), "l"(c));
    return d;
}
__device__ __forceinline__ unsigned long long pack2(float a, float b) {
    unsigned long long r;
    asm("mov.b64 %0, {%1, %2};" : "=l"(r) : "f"(a), "f"(b));
    return r;
}
__device__ __forceinline__ void unpack2(unsigned long long v, float& a, float& b) {
    asm("mov.b64 {%0, %1}, %2;" : "=f"(a), "=f"(b) : "l"(v));
}

// ---------------------------------------------------------------------------
// Reductions
// ---------------------------------------------------------------------------
__device__ __forceinline__ float warpReduceSum(float v) {
    #pragma unroll
    for (int o = 16; o > 0; o >>= 1)
        v += __shfl_down_sync(0xffffffffu, v, o);
    return v;
}

__device__ __forceinline__ float blockReduceSum(float v) {
    __shared__ float sbuf[32];
    int lane = threadIdx.x & 31;
    int wid  = threadIdx.x >> 5;
    v = warpReduceSum(v);
    __syncthreads();
    if (lane == 0) sbuf[wid] = v;
    __syncthreads();
    if (wid == 0) {
        int nw = (blockDim.x + 31) >> 5;
        v = (lane < nw) ? sbuf[lane] : 0.f;
        v = warpReduceSum(v);
    }
    return v;
}

// ---------------------------------------------------------------------------
// Helpers for cldice
// ---------------------------------------------------------------------------
__device__ __forceinline__ float4 f4min3(float4 a, float4 b, float4 c) {
    float4 o;
    o.x = fminf(a.x, fminf(b.x, c.x));
    o.y = fminf(a.y, fminf(b.y, c.y));
    o.z = fminf(a.z, fminf(b.z, c.z));
    o.w = fminf(a.w, fminf(b.w, c.w));
    return o;
}
__device__ __forceinline__ float4 f4min2(float4 a, float4 b) {
    float4 o;
    o.x = fminf(a.x, b.x); o.y = fminf(a.y, b.y);
    o.z = fminf(a.z, b.z); o.w = fminf(a.w, b.w);
    return o;
}
__device__ __forceinline__ float4 wmin(float4 v, int lane) {
    float l = __shfl_up_sync(0xffffffffu, v.w, 1);
    float r = __shfl_down_sync(0xffffffffu, v.x, 1);
    if (lane == 0)  l = INFINITY;
    if (lane == 31) r = INFINITY;
    const float m01 = fminf(v.x, v.y);
    const float m12 = fminf(v.y, v.z);
    const float m23 = fminf(v.z, v.w);
    float4 o;
    o.x = fminf(l, m01);
    o.y = fminf(m01, v.z);
    o.z = fminf(m12, v.w);
    o.w = fminf(m23, r);
    return o;
}

// ---------------------------------------------------------------------------
// MEGA KERNEL: chamfer + cldice + depth, type-segregated (round-8 layout,
// byte-identical — measured 40.7us on a clean run).
// ---------------------------------------------------------------------------
__global__ __launch_bounds__(256) void mega_kernel(
    const float* __restrict__ pred_centers, const float* __restrict__ gt_points,
    const float* __restrict__ pv, const float* __restrict__ gv,
    const float* __restrict__ pdep, const float* __restrict__ gdep,
    const float* __restrict__ mask)
{
    const int bx  = blockIdx.x;
    const int tid = threadIdx.x;

    if (bx < CH_BLOCKS) {
        // ===== Chamfer: f32x2 packed, 4 queries/thread, RED.MAX scoreboard ==
        const int xq    = bx & 7;            // 8 x-tiles of 1024 queries
        const int chunk = (bx >> 3) & 31;    // 32 candidate chunks of 256
        const int bz    = bx >> 8;
        const int b     = bz & 1;
        const int dir   = bz >> 1;

        const float* Q = (dir ? gt_points : pred_centers) + (size_t)b * NPTS * 3;
        const float* T = (dir ? pred_centers : gt_points) + (size_t)b * NPTS * 3;

        const int pt0 = xq * (256 * QBLK) + tid;
        const int pt1 = pt0 + 256, pt2 = pt0 + 512, pt3 = pt0 + 768;

        const float q0x = Q[pt0*3+0], q0y = Q[pt0*3+1], q0z = Q[pt0*3+2];
        const float q1x = Q[pt1*3+0], q1y = Q[pt1*3+1], q1z = Q[pt1*3+2];
        const float q2x = Q[pt2*3+0], q2y = Q[pt2*3+1], q2z = Q[pt2*3+2];
        const float q3x = Q[pt3*3+0], q3y = Q[pt3*3+1], q3z = Q[pt3*3+2];
        const unsigned long long q0x2 = pack2(q0x,q0x), q0y2 = pack2(q0y,q0y), q0z2 = pack2(q0z,q0z);
        const unsigned long long q1x2 = pack2(q1x,q1x), q1y2 = pack2(q1y,q1y), q1z2 = pack2(q1z,q1z);
        const unsigned long long q2x2 = pack2(q2x,q2x), q2y2 = pack2(q2y,q2y), q2z2 = pack2(q2z,q2z);
        const unsigned long long q3x2 = pack2(q3x,q3x), q3y2 = pack2(q3y,q3y), q3z2 = pack2(q3z,q3z);

        __shared__ ulonglong2 s_xy[TILE / 2];
        __shared__ ulonglong2 s_zw[TILE / 2];

        // load one 256-candidate tile (pre-scaled by -2, |g|^2 in w)
        {
            const int j = chunk * CHUNK_SZ + tid;
            const float gx = T[j*3+0], gy = T[j*3+1], gz = T[j*3+2];
            float* fxy = (float*)s_xy;
            float* fzw = (float*)s_zw;
            const int k4 = (tid >> 1) * 4 + (tid & 1);
            fxy[k4]     = -2.f * gx;
            fxy[k4 + 2] = -2.f * gy;
            fzw[k4]     = -2.f * gz;
            fzw[k4 + 2] = fmaf(gx, gx, fmaf(gy, gy, gz * gz));
        }
        __syncthreads();

        float m0l = INFINITY, m0h = INFINITY, m1l = INFINITY, m1h = INFINITY;
        float m2l = INFINITY, m2h = INFINITY, m3l = INFINITY, m3h = INFINITY;

        #pragma unroll 4
        for (int k = 0; k < TILE / 2; k++) {
            const ulonglong2 xy = s_xy[k];
            const ulonglong2 zw = s_zw[k];
            unsigned long long a0 = fma2(q0x2, xy.x, zw.y);
            unsigned long long a1 = fma2(q1x2, xy.x, zw.y);
            unsigned long long a2 = fma2(q2x2, xy.x, zw.y);
            unsigned long long a3 = fma2(q3x2, xy.x, zw.y);
            a0 = fma2(q0y2, xy.y, a0);
            a1 = fma2(q1y2, xy.y, a1);
            a2 = fma2(q2y2, xy.y, a2);
            a3 = fma2(q3y2, xy.y, a3);
            a0 = fma2(q0z2, zw.x, a0);
            a1 = fma2(q1z2, zw.x, a1);
            a2 = fma2(q2z2, zw.x, a2);
            a3 = fma2(q3z2, zw.x, a3);
            float lo, hi;
            unpack2(a0, lo, hi); m0l = fminf(m0l, lo); m0h = fminf(m0h, hi);
            unpack2(a1, lo, hi); m1l = fminf(m1l, lo); m1h = fminf(m1h, hi);
            unpack2(a2, lo, hi); m2l = fminf(m2l, lo); m2h = fminf(m2h, hi);
            unpack2(a3, lo, hi); m3l = fminf(m3l, lo); m3h = fminf(m3h, hi);
        }
        // fold in |q|^2 and publish via order-independent RED.MAX
        const float q02 = fmaf(q0x, q0x, fmaf(q0y, q0y, q0z * q0z));
        const float q12 = fmaf(q1x, q1x, fmaf(q1y, q1y, q1z * q1z));
        const float q22 = fmaf(q2x, q2x, fmaf(q2y, q2y, q2z * q2z));
        const float q32 = fmaf(q3x, q3x, fmaf(q3y, q3y, q3z * q3z));
        const int slot = (dir * 2 + b) * NPTS;
        atomicMax(&g_min[slot + pt0], enc_min(fminf(m0l, m0h) + q02));
        atomicMax(&g_min[slot + pt1], enc_min(fminf(m1l, m1h) + q12));
        atomicMax(&g_min[slot + pt2], enc_min(fminf(m2l, m2h) + q22));
        atomicMax(&g_min[slot + pt3], enc_min(fminf(m3l, m3h) + q32));

    } else if (bx < CH_BLOCKS + CL_BLOCKS) {
        // ===== clDice: fused separable 3x3x3 min-pool + sigmoid + reduce ====
        const int bi   = bx - CH_BLOCKS;
        const int lane = tid & 31;
        const int wid  = tid >> 5;
        const int h    = (bi & 15) * 8 + wid;
        const int d0   = ((bi >> 4) & 15) * DCHUNK;
        const int b    = bi >> 8;
        const float* P = pv + (size_t)b * VOL_PER_B;
        const float* G = gv + (size_t)b * VOL_PER_B;
        const bool hm = (h > 0), hp = (h < VH - 1);
        const int col = lane * 4;

        const float4 inf4 = make_float4(INFINITY, INFINITY, INFINITY, INFINITY);
        float4 wa_p = inf4, wb_p = inf4, wa_g = inf4, wb_g = inf4;
        float accI = 0.f, accP = 0.f, accG = 0.f;

        for (int dd = d0 - 1; dd <= d0 + DCHUNK; dd++) {
            float4 ph = inf4, gh = inf4;
            if (dd >= 0 && dd < VD) {
                const size_t rb = (size_t)dd * (VH * VW) + h * VW + col;
                ph = *(const float4*)(P + rb);
                gh = *(const float4*)(G + rb);
                if (hm) {
                    ph = f4min2(ph, *(const float4*)(P + rb - VW));
                    gh = f4min2(gh, *(const float4*)(G + rb - VW));
                }
                if (hp) {
                    ph = f4min2(ph, *(const float4*)(P + rb + VW));
                    gh = f4min2(gh, *(const float4*)(G + rb + VW));
                }
            }
            const float4 pc = wmin(ph, lane);
            const float4 gc = wmin(gh, lane);
            if (dd > d0) {
                const float4 pe = f4min3(wa_p, wb_p, pc);
                const float4 ge = f4min3(wa_g, wb_g, gc);
                const float s0 = 1.f / (1.f + __expf(-pe.x));
                const float s1 = 1.f / (1.f + __expf(-pe.y));
                const float s2 = 1.f / (1.f + __expf(-pe.z));
                const float s3 = 1.f / (1.f + __expf(-pe.w));
                accI = fmaf(s0, ge.x, fmaf(s1, ge.y, fmaf(s2, ge.z, fmaf(s3, ge.w, accI))));
                accP += (s0 + s1) + (s2 + s3);
                accG += (ge.x + ge.y) + (ge.z + ge.w);
            }
            wa_p = wb_p; wb_p = pc;
            wa_g = wb_g; wb_g = gc;
        }

        float r;
        r = blockReduceSum(accI); if (tid == 0) atomicAdd(&g_acc.inter[b], (double)r);
        r = blockReduceSum(accP); if (tid == 0) atomicAdd(&g_acc.psum[b], (double)r);
        r = blockReduceSum(accG); if (tid == 0) atomicAdd(&g_acc.gsum[b], (double)r);

    } else {
        // ===== Depth loss: SILog + gradient L1 + masked L1, float4 ==========
        const int bi = bx - CH_BLOCKS - CL_BLOCKS;
        const int vi = bi * 256 + tid;
        const int i  = vi * 4;
        const int b  = i >> 18;
        const int w0 = i & (DW - 1);
        const int h  = (i >> 9) & (DH - 1);

        const float4 p  = ((const float4*)pdep)[vi];
        const float4 g  = ((const float4*)gdep)[vi];
        const float4 mk = ((const float4*)mask)[vi];

        float lg0 = __logf(p.x + 0.1f) - __logf(g.x + 0.1f);
        float lg1 = __logf(p.y + 0.1f) - __logf(g.y + 0.1f);
        float lg2 = __logf(p.z + 0.1f) - __logf(g.z + 0.1f);
        float lg3 = __logf(p.w + 0.1f) - __logf(g.w + 0.1f);
        float s_g  = lg0 + lg1 + lg2 + lg3;
        float s_g2 = fmaf(lg0, lg0, fmaf(lg1, lg1, fmaf(lg2, lg2, lg3 * lg3)));

        float s_gx = 0.f;
        if (h < DH - 1) {
            const float4 pd = ((const float4*)pdep)[vi + DW / 4];
            const float4 gd = ((const float4*)gdep)[vi + DW / 4];
            s_gx += fabsf(fabsf(p.x - pd.x) - fabsf(g.x - gd.x));
            s_gx += fabsf(fabsf(p.y - pd.y) - fabsf(g.y - gd.y));
            s_gx += fabsf(fabsf(p.z - pd.z) - fabsf(g.z - gd.z));
            s_gx += fabsf(fabsf(p.w - pd.w) - fabsf(g.w - gd.w));
        }
        float s_gy = 0.f;
        s_gy += fabsf(fabsf(p.x - p.y) - fabsf(g.x - g.y));
        s_gy += fabsf(fabsf(p.y - p.z) - fabsf(g.y - g.z));
        s_gy += fabsf(fabsf(p.z - p.w) - fabsf(g.z - g.w));
        if (w0 + 4 < DW) {
            const float pn = pdep[i + 4];
            const float gn = gdep[i + 4];
            s_gy += fabsf(fabsf(p.w - pn) - fabsf(g.w - gn));
        }
        float s_mn = fabsf(p.x - g.x) * mk.x + fabsf(p.y - g.y) * mk.y
                   + fabsf(p.z - g.z) * mk.z + fabsf(p.w - g.w) * mk.w;
        float s_md = mk.x + mk.y + mk.z + mk.w;

        float r;
        r = blockReduceSum(s_g);  if (tid == 0) atomicAdd(&g_acc.g_sum[b],  (double)r);
        r = blockReduceSum(s_g2); if (tid == 0) atomicAdd(&g_acc.g2_sum[b], (double)r);
        r = blockReduceSum(s_gx); if (tid == 0) atomicAdd(&g_acc.gradx,    (double)r);
        r = blockReduceSum(s_gy); if (tid == 0) atomicAdd(&g_acc.grady,    (double)r);
        r = blockReduceSum(s_mn); if (tid == 0) atomicAdd(&g_acc.mask_num, (double)r);
        r = blockReduceSum(s_md); if (tid == 0) atomicAdd(&g_acc.mask_den, (double)r);
    }
}

// ---------------------------------------------------------------------------
// FINALIZE: one block, 1024 threads, float scalar algebra (sm_103a FP64
// div/log chains are us-scale; float version measured 7.8us vs 11.0us).
// Scans + resets the 128KB g_min table with streaming (cg) loads.
// ---------------------------------------------------------------------------
__global__ __launch_bounds__(1024) void finalize_kernel(
    const int* __restrict__ iter_ptr, float* __restrict__ out)
{
    const int tid = threadIdx.x;
    uint4* gm = (uint4*)g_min;          // NMIN/4 = 8192 uint4
    const uint4 z4 = make_uint4(0u, 0u, 0u, 0u);

    uint4 v[8];
    #pragma unroll
    for (int k = 0; k < 8; k++)
        v[k] = __ldcg(&gm[tid + k * 1024]);   // batched streaming loads
    #pragma unroll
    for (int k = 0; k < 8; k++) gm[tid + k * 1024] = z4;     // reset table

    float csum = 0.f;
    #pragma unroll
    for (int k = 0; k < 8; k++)
        csum += (dec_min(v[k].x) + dec_min(v[k].y))
              + (dec_min(v[k].z) + dec_min(v[k].w));

    const float ctot = blockReduceSum(csum);

    if (tid >= 32) return;
    const int lane = tid;
    __shared__ double s_acc[ACC_N];
    volatile double* gptr = (volatile double*)&g_acc;
    if (lane < ACC_N) s_acc[lane] = gptr[lane];     // parallel loads
    __syncwarp();
    if (lane < ACC_N) gptr[lane] = 0.0;             // re-zero for next replay

    if (lane == 0) {
        const float inter0 = (float)s_acc[0], inter1 = (float)s_acc[1];
        const float psum0  = (float)s_acc[2], psum1  = (float)s_acc[3];
        const float gsum0  = (float)s_acc[4], gsum1  = (float)s_acc[5];
        const float gs0    = (float)s_acc[6], gs1    = (float)s_acc[7];
        const float g2s0   = (float)s_acc[8], g2s1   = (float)s_acc[9];
        const float gradx  = (float)s_acc[10], grady = (float)s_acc[11];
        const float mnum   = (float)s_acc[12], mden  = (float)s_acc[13];

        const float chamfer = ctot / (float)(BATCH * NPTS);

        const float smooth = 1e-5f;
        const float dice0 = (2.f * inter0 + smooth) / (psum0 + gsum0 + smooth);
        const float dice1 = (2.f * inter1 + smooth) / (psum1 + gsum1 + smooth);
        const float cldice = 1.f - 0.5f * (dice0 + dice1);

        const float Np = (float)DPIX_PER_B;
        const float m0 = gs0 / Np, m1 = gs1 / Np;
        const float v0 = g2s0 / Np - m0 * m0;
        const float v1 = g2s1 / Np - m1 * m1;
        const float silog = 10.f * 0.5f * (v0 + v1) + 10.f * 0.5f * (m0 * m0 + m1 * m1);
        const float grad = gradx / (float)(BATCH * (DH - 1) * DW)
                         + grady / (float)(BATCH * DH * (DW - 1));
        const float mask_l1 = mnum / (mden + 1e-8f);
        const float dloss = silog + grad + mask_l1;

        int it = *iter_ptr;
        if (it < 1) it = 1;
        const float gamma1 = 2.f * __logf((float)it / 20000.f);

        out[0] = gamma1 * chamfer + 0.5f * cldice + 0.01f * dloss;
    }
}

// ---------------------------------------------------------------------------
// Launch: two kernels (boundary = grid-wide fence; no per-block membars)
// ---------------------------------------------------------------------------
extern "C" void kernel_launch(void* const* d_in, const int* in_sizes, int n_in,
                              void* d_out, int out_size) {
    const float* pred_centers = (const float*)d_in[0];
    const float* pred_volume  = (const float*)d_in[1];
    const float* pred_depth   = (const float*)d_in[2];
    const float* gt_points    = (const float*)d_in[3];
    const float* gt_volume    = (const float*)d_in[4];
    const float* gt_depth     = (const float*)d_in[5];
    const float* depth_mask   = (const float*)d_in[6];
    const int*   iteration    = (const int*)d_in[7];
    float* out = (float*)d_out;

    mega_kernel<<<ALL_BLOCKS, 256>>>(pred_centers, gt_points,
                                     pred_volume, gt_volume,
                                     pred_depth, gt_depth, depth_mask);

    finalize_kernel<<<1, 1024>>>(iteration, out);
}

// round 15
// speedup vs baseline: 1.0383x; 1.0383x over previous
#include <cuda_runtime.h>
#include <cuda_bf16.h>
#include <math.h>

// ---------------------------------------------------------------------------
// Problem constants (fixed shapes from metadata)
// ---------------------------------------------------------------------------
#define BATCH   2
#define NPTS    8192
#define CHUNKS  32
#define CHUNK_SZ (NPTS / CHUNKS)   // 256
#define TILE    256
#define QBLK    4                  // queries per thread
#define XTILES  (NPTS / (256 * QBLK))   // 8

#define VD 64
#define VH 128
#define VW 128
#define VOL_PER_B (VD * VH * VW)
#define DCHUNK 4

#define DH 512
#define DW 512
#define DPIX_PER_B (DH * DW)
#define DPIX_TOT   (BATCH * DPIX_PER_B)

// mega-kernel block partition: TYPE-SEGREGATED, chamfer (longest jobs) first.
#define CH_BLOCKS 1024
#define CL_BLOCKS 512
#define DP_BLOCKS 512
#define ALL_BLOCKS (CH_BLOCKS + CL_BLOCKS + DP_BLOCKS)   // 2048

#define NMIN (4 * NPTS)            // [dir][b][pt] min table, 32768 entries

// finalize partition
#define FIN_BLOCKS 32
#define FIN_THREADS 256

// ---------------------------------------------------------------------------
// Device scratch (static — no allocations allowed)
// ---------------------------------------------------------------------------
struct Acc {
    double inter[2], psum[2], gsum[2];
    double g_sum[2], g2_sum[2];
    double gradx, grady, mask_num, mask_den;
};
#define ACC_N 14
__device__ Acc g_acc;                 // zero-init; re-zeroed by finalize tail
__device__ double g_chamfer_sum;      // zero-init; re-zeroed by finalize tail
__device__ unsigned int g_fin_ctr;    // zero-init; reset by finalize tail
__device__ unsigned int g_min[NMIN];  // zero-init (= +inf identity); reset by finalize

// ---------------------------------------------------------------------------
// Monotone float<->uint encoding: min over floats == max over codes, with 0
// as the identity (no real float encodes to 0).
// ---------------------------------------------------------------------------
__device__ __forceinline__ unsigned int enc_min(float f) {
    unsigned int u = __float_as_uint(f);
    return (u & 0x80000000u) ? u : ((~u) & 0x7FFFFFFFu);
}
__device__ __forceinline__ float dec_min(unsigned int rk) {
    return (rk & 0x80000000u) ? __uint_as_float(rk)
                              : __uint_as_float((~rk) & 0x7FFFFFFFu);
}

// ---------------------------------------------------------------------------
// f32x2 packed helpers (sm_103a; ptxas will not auto-fuse — must be PTX)
// ---------------------------------------------------------------------------
__device__ __forceinline__ unsigned long long fma2(unsigned long long a,
                                                   unsigned long long b,
                                                   unsigned long long c) {
    unsigned long long d;
    asm("fma.rn.f32x2 %0, %1, %2, %3;" : "=l"(d) : "l"(a), "l"(b), "l"(c));
    return d;
}
__device__ __forceinline__ unsigned long long pack2(float a, float b) {
    unsigned long long r;
    asm("mov.b64 %0, {%1, %2};" : "=l"(r) : "f"(a), "f"(b));
    return r;
}
__device__ __forceinline__ void unpack2(unsigned long long v, float& a, float& b) {
    asm("mov.b64 {%0, %1}, %2;" : "=f"(a), "=f"(b) : "l"(v));
}

// ---------------------------------------------------------------------------
// Reductions
// ---------------------------------------------------------------------------
__device__ __forceinline__ float warpReduceSum(float v) {
    #pragma unroll
    for (int o = 16; o > 0; o >>= 1)
        v += __shfl_down_sync(0xffffffffu, v, o);
    return v;
}

__device__ __forceinline__ float blockReduceSum(float v) {
    __shared__ float sbuf[32];
    int lane = threadIdx.x & 31;
    int wid  = threadIdx.x >> 5;
    v = warpReduceSum(v);
    __syncthreads();
    if (lane == 0) sbuf[wid] = v;
    __syncthreads();
    if (wid == 0) {
        int nw = (blockDim.x + 31) >> 5;
        v = (lane < nw) ? sbuf[lane] : 0.f;
        v = warpReduceSum(v);
    }
    return v;
}

// ---------------------------------------------------------------------------
// Helpers for cldice
// ---------------------------------------------------------------------------
__device__ __forceinline__ float4 f4min3(float4 a, float4 b, float4 c) {
    float4 o;
    o.x = fminf(a.x, fminf(b.x, c.x));
    o.y = fminf(a.y, fminf(b.y, c.y));
    o.z = fminf(a.z, fminf(b.z, c.z));
    o.w = fminf(a.w, fminf(b.w, c.w));
    return o;
}
__device__ __forceinline__ float4 f4min2(float4 a, float4 b) {
    float4 o;
    o.x = fminf(a.x, b.x); o.y = fminf(a.y, b.y);
    o.z = fminf(a.z, b.z); o.w = fminf(a.w, b.w);
    return o;
}
__device__ __forceinline__ float4 wmin(float4 v, int lane) {
    float l = __shfl_up_sync(0xffffffffu, v.w, 1);
    float r = __shfl_down_sync(0xffffffffu, v.x, 1);
    if (lane == 0)  l = INFINITY;
    if (lane == 31) r = INFINITY;
    const float m01 = fminf(v.x, v.y);
    const float m12 = fminf(v.y, v.z);
    const float m23 = fminf(v.z, v.w);
    float4 o;
    o.x = fminf(l, m01);
    o.y = fminf(m01, v.z);
    o.z = fminf(m12, v.w);
    o.w = fminf(m23, r);
    return o;
}

// ---------------------------------------------------------------------------
// MEGA KERNEL: chamfer + cldice + depth, type-segregated (measured-good,
// byte-identical to round-8/14 layout).
// ---------------------------------------------------------------------------
__global__ __launch_bounds__(256) void mega_kernel(
    const float* __restrict__ pred_centers, const float* __restrict__ gt_points,
    const float* __restrict__ pv, const float* __restrict__ gv,
    const float* __restrict__ pdep, const float* __restrict__ gdep,
    const float* __restrict__ mask)
{
    const int bx  = blockIdx.x;
    const int tid = threadIdx.x;

    if (bx < CH_BLOCKS) {
        // ===== Chamfer: f32x2 packed, 4 queries/thread, RED.MAX scoreboard ==
        const int xq    = bx & 7;            // 8 x-tiles of 1024 queries
        const int chunk = (bx >> 3) & 31;    // 32 candidate chunks of 256
        const int bz    = bx >> 8;
        const int b     = bz & 1;
        const int dir   = bz >> 1;

        const float* Q = (dir ? gt_points : pred_centers) + (size_t)b * NPTS * 3;
        const float* T = (dir ? pred_centers : gt_points) + (size_t)b * NPTS * 3;

        const int pt0 = xq * (256 * QBLK) + tid;
        const int pt1 = pt0 + 256, pt2 = pt0 + 512, pt3 = pt0 + 768;

        const float q0x = Q[pt0*3+0], q0y = Q[pt0*3+1], q0z = Q[pt0*3+2];
        const float q1x = Q[pt1*3+0], q1y = Q[pt1*3+1], q1z = Q[pt1*3+2];
        const float q2x = Q[pt2*3+0], q2y = Q[pt2*3+1], q2z = Q[pt2*3+2];
        const float q3x = Q[pt3*3+0], q3y = Q[pt3*3+1], q3z = Q[pt3*3+2];
        const unsigned long long q0x2 = pack2(q0x,q0x), q0y2 = pack2(q0y,q0y), q0z2 = pack2(q0z,q0z);
        const unsigned long long q1x2 = pack2(q1x,q1x), q1y2 = pack2(q1y,q1y), q1z2 = pack2(q1z,q1z);
        const unsigned long long q2x2 = pack2(q2x,q2x), q2y2 = pack2(q2y,q2y), q2z2 = pack2(q2z,q2z);
        const unsigned long long q3x2 = pack2(q3x,q3x), q3y2 = pack2(q3y,q3y), q3z2 = pack2(q3z,q3z);

        __shared__ ulonglong2 s_xy[TILE / 2];
        __shared__ ulonglong2 s_zw[TILE / 2];

        // load one 256-candidate tile (pre-scaled by -2, |g|^2 in w)
        {
            const int j = chunk * CHUNK_SZ + tid;
            const float gx = T[j*3+0], gy = T[j*3+1], gz = T[j*3+2];
            float* fxy = (float*)s_xy;
            float* fzw = (float*)s_zw;
            const int k4 = (tid >> 1) * 4 + (tid & 1);
            fxy[k4]     = -2.f * gx;
            fxy[k4 + 2] = -2.f * gy;
            fzw[k4]     = -2.f * gz;
            fzw[k4 + 2] = fmaf(gx, gx, fmaf(gy, gy, gz * gz));
        }
        __syncthreads();

        float m0l = INFINITY, m0h = INFINITY, m1l = INFINITY, m1h = INFINITY;
        float m2l = INFINITY, m2h = INFINITY, m3l = INFINITY, m3h = INFINITY;

        #pragma unroll 4
        for (int k = 0; k < TILE / 2; k++) {
            const ulonglong2 xy = s_xy[k];
            const ulonglong2 zw = s_zw[k];
            unsigned long long a0 = fma2(q0x2, xy.x, zw.y);
            unsigned long long a1 = fma2(q1x2, xy.x, zw.y);
            unsigned long long a2 = fma2(q2x2, xy.x, zw.y);
            unsigned long long a3 = fma2(q3x2, xy.x, zw.y);
            a0 = fma2(q0y2, xy.y, a0);
            a1 = fma2(q1y2, xy.y, a1);
            a2 = fma2(q2y2, xy.y, a2);
            a3 = fma2(q3y2, xy.y, a3);
            a0 = fma2(q0z2, zw.x, a0);
            a1 = fma2(q1z2, zw.x, a1);
            a2 = fma2(q2z2, zw.x, a2);
            a3 = fma2(q3z2, zw.x, a3);
            float lo, hi;
            unpack2(a0, lo, hi); m0l = fminf(m0l, lo); m0h = fminf(m0h, hi);
            unpack2(a1, lo, hi); m1l = fminf(m1l, lo); m1h = fminf(m1h, hi);
            unpack2(a2, lo, hi); m2l = fminf(m2l, lo); m2h = fminf(m2h, hi);
            unpack2(a3, lo, hi); m3l = fminf(m3l, lo); m3h = fminf(m3h, hi);
        }
        // fold in |q|^2 and publish via order-independent RED.MAX
        const float q02 = fmaf(q0x, q0x, fmaf(q0y, q0y, q0z * q0z));
        const float q12 = fmaf(q1x, q1x, fmaf(q1y, q1y, q1z * q1z));
        const float q22 = fmaf(q2x, q2x, fmaf(q2y, q2y, q2z * q2z));
        const float q32 = fmaf(q3x, q3x, fmaf(q3y, q3y, q3z * q3z));
        const int slot = (dir * 2 + b) * NPTS;
        atomicMax(&g_min[slot + pt0], enc_min(fminf(m0l, m0h) + q02));
        atomicMax(&g_min[slot + pt1], enc_min(fminf(m1l, m1h) + q12));
        atomicMax(&g_min[slot + pt2], enc_min(fminf(m2l, m2h) + q22));
        atomicMax(&g_min[slot + pt3], enc_min(fminf(m3l, m3h) + q32));

    } else if (bx < CH_BLOCKS + CL_BLOCKS) {
        // ===== clDice: fused separable 3x3x3 min-pool + sigmoid + reduce ====
        const int bi   = bx - CH_BLOCKS;
        const int lane = tid & 31;
        const int wid  = tid >> 5;
        const int h    = (bi & 15) * 8 + wid;
        const int d0   = ((bi >> 4) & 15) * DCHUNK;
        const int b    = bi >> 8;
        const float* P = pv + (size_t)b * VOL_PER_B;
        const float* G = gv + (size_t)b * VOL_PER_B;
        const bool hm = (h > 0), hp = (h < VH - 1);
        const int col = lane * 4;

        const float4 inf4 = make_float4(INFINITY, INFINITY, INFINITY, INFINITY);
        float4 wa_p = inf4, wb_p = inf4, wa_g = inf4, wb_g = inf4;
        float accI = 0.f, accP = 0.f, accG = 0.f;

        for (int dd = d0 - 1; dd <= d0 + DCHUNK; dd++) {
            float4 ph = inf4, gh = inf4;
            if (dd >= 0 && dd < VD) {
                const size_t rb = (size_t)dd * (VH * VW) + h * VW + col;
                ph = *(const float4*)(P + rb);
                gh = *(const float4*)(G + rb);
                if (hm) {
                    ph = f4min2(ph, *(const float4*)(P + rb - VW));
                    gh = f4min2(gh, *(const float4*)(G + rb - VW));
                }
                if (hp) {
                    ph = f4min2(ph, *(const float4*)(P + rb + VW));
                    gh = f4min2(gh, *(const float4*)(G + rb + VW));
                }
            }
            const float4 pc = wmin(ph, lane);
            const float4 gc = wmin(gh, lane);
            if (dd > d0) {
                const float4 pe = f4min3(wa_p, wb_p, pc);
                const float4 ge = f4min3(wa_g, wb_g, gc);
                const float s0 = 1.f / (1.f + __expf(-pe.x));
                const float s1 = 1.f / (1.f + __expf(-pe.y));
                const float s2 = 1.f / (1.f + __expf(-pe.z));
                const float s3 = 1.f / (1.f + __expf(-pe.w));
                accI = fmaf(s0, ge.x, fmaf(s1, ge.y, fmaf(s2, ge.z, fmaf(s3, ge.w, accI))));
                accP += (s0 + s1) + (s2 + s3);
                accG += (ge.x + ge.y) + (ge.z + ge.w);
            }
            wa_p = wb_p; wb_p = pc;
            wa_g = wb_g; wb_g = gc;
        }

        float r;
        r = blockReduceSum(accI); if (tid == 0) atomicAdd(&g_acc.inter[b], (double)r);
        r = blockReduceSum(accP); if (tid == 0) atomicAdd(&g_acc.psum[b], (double)r);
        r = blockReduceSum(accG); if (tid == 0) atomicAdd(&g_acc.gsum[b], (double)r);

    } else {
        // ===== Depth loss: SILog + gradient L1 + masked L1, float4 ==========
        const int bi = bx - CH_BLOCKS - CL_BLOCKS;
        const int vi = bi * 256 + tid;
        const int i  = vi * 4;
        const int b  = i >> 18;
        const int w0 = i & (DW - 1);
        const int h  = (i >> 9) & (DH - 1);

        const float4 p  = ((const float4*)pdep)[vi];
        const float4 g  = ((const float4*)gdep)[vi];
        const float4 mk = ((const float4*)mask)[vi];

        float lg0 = __logf(p.x + 0.1f) - __logf(g.x + 0.1f);
        float lg1 = __logf(p.y + 0.1f) - __logf(g.y + 0.1f);
        float lg2 = __logf(p.z + 0.1f) - __logf(g.z + 0.1f);
        float lg3 = __logf(p.w + 0.1f) - __logf(g.w + 0.1f);
        float s_g  = lg0 + lg1 + lg2 + lg3;
        float s_g2 = fmaf(lg0, lg0, fmaf(lg1, lg1, fmaf(lg2, lg2, lg3 * lg3)));

        float s_gx = 0.f;
        if (h < DH - 1) {
            const float4 pd = ((const float4*)pdep)[vi + DW / 4];
            const float4 gd = ((const float4*)gdep)[vi + DW / 4];
            s_gx += fabsf(fabsf(p.x - pd.x) - fabsf(g.x - gd.x));
            s_gx += fabsf(fabsf(p.y - pd.y) - fabsf(g.y - gd.y));
            s_gx += fabsf(fabsf(p.z - pd.z) - fabsf(g.z - gd.z));
            s_gx += fabsf(fabsf(p.w - pd.w) - fabsf(g.w - gd.w));
        }
        float s_gy = 0.f;
        s_gy += fabsf(fabsf(p.x - p.y) - fabsf(g.x - g.y));
        s_gy += fabsf(fabsf(p.y - p.z) - fabsf(g.y - g.z));
        s_gy += fabsf(fabsf(p.z - p.w) - fabsf(g.z - g.w));
        if (w0 + 4 < DW) {
            const float pn = pdep[i + 4];
            const float gn = gdep[i + 4];
            s_gy += fabsf(fabsf(p.w - pn) - fabsf(g.w - gn));
        }
        float s_mn = fabsf(p.x - g.x) * mk.x + fabsf(p.y - g.y) * mk.y
                   + fabsf(p.z - g.z) * mk.z + fabsf(p.w - g.w) * mk.w;
        float s_md = mk.x + mk.y + mk.z + mk.w;

        float r;
        r = blockReduceSum(s_g);  if (tid == 0) atomicAdd(&g_acc.g_sum[b],  (double)r);
        r = blockReduceSum(s_g2); if (tid == 0) atomicAdd(&g_acc.g2_sum[b], (double)r);
        r = blockReduceSum(s_gx); if (tid == 0) atomicAdd(&g_acc.gradx,    (double)r);
        r = blockReduceSum(s_gy); if (tid == 0) atomicAdd(&g_acc.grady,    (double)r);
        r = blockReduceSum(s_mn); if (tid == 0) atomicAdd(&g_acc.mask_num, (double)r);
        r = blockReduceSum(s_md); if (tid == 0) atomicAdd(&g_acc.mask_den, (double)r);
    }
}

// ---------------------------------------------------------------------------
// FINALIZE: 32 blocks x 256 threads. Each block scans+resets 1/32 of the
// g_min table (parallel across SMs — the single-block version bottlenecked
// one SM's L2 port at 8.4us), atomicAdds its partial chamfer sum, and the
// last block (ticket) computes the float scalar tail and re-zeroes state.
// ---------------------------------------------------------------------------
__global__ __launch_bounds__(FIN_THREADS) void finalize_kernel(
    const int* __restrict__ iter_ptr, float* __restrict__ out)
{
    const int tid = threadIdx.x;
    const int idx = blockIdx.x * FIN_THREADS + tid;   // 0..8191 (uint4 index)
    uint4* gm = (uint4*)g_min;

    const uint4 v = __ldcg(&gm[idx]);
    gm[idx] = make_uint4(0u, 0u, 0u, 0u);             // reset for next replay

    float csum = (dec_min(v.x) + dec_min(v.y)) + (dec_min(v.z) + dec_min(v.w));
    const float r = blockReduceSum(csum);

    __shared__ int s_last;
    if (tid == 0) {
        atomicAdd(&g_chamfer_sum, (double)r);
        __threadfence();
        const unsigned int t = atomicAdd(&g_fin_ctr, 1u);
        s_last = (t == FIN_BLOCKS - 1) ? 1 : 0;
    }
    __syncthreads();
    if (!s_last || tid >= 32) return;

    // ----- last block, warp 0: scalar tail (float; FP64 chains are us-scale)
    const int lane = tid;
    __threadfence();
    __shared__ double s_acc[ACC_N + 1];
    volatile double* gptr = (volatile double*)&g_acc;
    if (lane < ACC_N) s_acc[lane] = gptr[lane];       // parallel loads
    if (lane == ACC_N) s_acc[ACC_N] = *(volatile double*)&g_chamfer_sum;
    __syncwarp();
    if (lane < ACC_N) gptr[lane] = 0.0;               // re-zero for next replay
    if (lane == ACC_N) *(volatile double*)&g_chamfer_sum = 0.0;
    if (lane == 0) g_fin_ctr = 0u;

    if (lane == 0) {
        const float inter0 = (float)s_acc[0], inter1 = (float)s_acc[1];
        const float psum0  = (float)s_acc[2], psum1  = (float)s_acc[3];
        const float gsum0  = (float)s_acc[4], gsum1  = (float)s_acc[5];
        const float gs0    = (float)s_acc[6], gs1    = (float)s_acc[7];
        const float g2s0   = (float)s_acc[8], g2s1   = (float)s_acc[9];
        const float gradx  = (float)s_acc[10], grady = (float)s_acc[11];
        const float mnum   = (float)s_acc[12], mden  = (float)s_acc[13];
        const float ctot   = (float)s_acc[14];

        const float chamfer = ctot / (float)(BATCH * NPTS);

        const float smooth = 1e-5f;
        const float dice0 = (2.f * inter0 + smooth) / (psum0 + gsum0 + smooth);
        const float dice1 = (2.f * inter1 + smooth) / (psum1 + gsum1 + smooth);
        const float cldice = 1.f - 0.5f * (dice0 + dice1);

        const float Np = (float)DPIX_PER_B;
        const float m0 = gs0 / Np, m1 = gs1 / Np;
        const float v0 = g2s0 / Np - m0 * m0;
        const float v1 = g2s1 / Np - m1 * m1;
        const float silog = 10.f * 0.5f * (v0 + v1) + 10.f * 0.5f * (m0 * m0 + m1 * m1);
        const float grad = gradx / (float)(BATCH * (DH - 1) * DW)
                         + grady / (float)(BATCH * DH * (DW - 1));
        const float mask_l1 = mnum / (mden + 1e-8f);
        const float dloss = silog + grad + mask_l1;

        int it = *iter_ptr;
        if (it < 1) it = 1;
        const float gamma1 = 2.f * __logf((float)it / 20000.f);

        out[0] = gamma1 * chamfer + 0.5f * cldice + 0.01f * dloss;
    }
}

// ---------------------------------------------------------------------------
// Launch: two kernels (boundary = grid-wide fence; no per-block membars)
// ---------------------------------------------------------------------------
extern "C" void kernel_launch(void* const* d_in, const int* in_sizes, int n_in,
                              void* d_out, int out_size) {
    const float* pred_centers = (const float*)d_in[0];
    const float* pred_volume  = (const float*)d_in[1];
    const float* pred_depth   = (const float*)d_in[2];
    const float* gt_points    = (const float*)d_in[3];
    const float* gt_volume    = (const float*)d_in[4];
    const float* gt_depth     = (const float*)d_in[5];
    const float* depth_mask   = (const float*)d_in[6];
    const int*   iteration    = (const int*)d_in[7];
    float* out = (float*)d_out;

    mega_kernel<<<ALL_BLOCKS, 256>>>(pred_centers, gt_points,
                                     pred_volume, gt_volume,
                                     pred_depth, gt_depth, depth_mask);

    finalize_kernel<<<FIN_BLOCKS, FIN_THREADS>>>(iteration, out);
}